// round 14
// baseline (speedup 1.0000x reference)
#include <cuda_runtime.h>

#define BB 64
#define TT 512
#define II 512
#define HH 1024

// Recurrence tiling: 128 CTAs = 4 row-groups (16 rows) x 32 col-groups (32 cols).
#define RG_ROWS 16
#define CG_COLS 32
#define KS 8                      // k-split ways
#define PB_STRIDE 44              // pbuf row stride (floats)
#define PB_PLANE (RG_ROWS * PB_STRIDE)

#define WS_FLOATS (1024 * CG_COLS)              // 32768
#define HS_FLOATS (RG_ROWS * 1024 + 4 * 8)      // 16416 (8-float pad per 4-row group)
#define PB_FLOATS (KS * PB_PLANE)               // 5632

// h double buffer (ring) + per-row-group monotone barrier counters.
__device__ float g_h[2][BB * HH];
__device__ unsigned g_cnt[4 * 64];

// ---------------------------------------------------------------------------
// Packed f32x2 helpers (Blackwell FFMA2 — only reachable via PTX fma.rn.f32x2).
// ---------------------------------------------------------------------------
__device__ __forceinline__ unsigned long long pack2(float v) {
    unsigned long long r;
    asm("mov.b64 %0, {%1, %1};" : "=l"(r) : "f"(v));
    return r;
}
__device__ __forceinline__ void fma2(unsigned long long& d,
                                     unsigned long long a,
                                     unsigned long long b) {
    asm("fma.rn.f32x2 %0, %1, %2, %0;" : "+l"(d) : "l"(a), "l"(b));
}
__device__ __forceinline__ void unpack2(unsigned long long v, float& lo, float& hi) {
    asm("mov.b64 {%0, %1}, %2;" : "=f"(lo), "=f"(hi) : "l"(v));
}
__device__ __forceinline__ unsigned long long dl(double d) {
    return __double_as_longlong(d);
}

// ---------------------------------------------------------------------------
// Phase 1: x_proj = inputs(32768x512) @ W_xh(512x1024) + b  -> written to out.
// 128x128 tile, 8x8 microtile, BK=16, packed FFMA2 inner product.
// CTA (0,0) additionally resets the rg barrier counters and stages h_prev
// into ring[0] (stream order guarantees visibility to rnn_recur).
// ---------------------------------------------------------------------------
__global__ __launch_bounds__(256, 2) void xproj_gemm(
    const float* __restrict__ A, const float* __restrict__ W,
    const float* __restrict__ bias, const float* __restrict__ h_prev,
    float* __restrict__ C) {
    __shared__ __align__(16) float As[16][128];   // As[k][m]
    __shared__ __align__(16) float Bs[16][128];   // Bs[k][n]

    const int tid = threadIdx.x;

    // Merged init (one CTA): counters = 0, ring[0] = h_prev.
    if (blockIdx.x == 0 && blockIdx.y == 0) {
        if (tid < 4) g_cnt[tid * 64] = 0u;
        const float4* hp4 = (const float4*)h_prev;
        float4* r0 = (float4*)g_h[0];
#pragma unroll
        for (int i = 0; i < 64; i++)
            r0[tid + i * 256] = hp4[tid + i * 256];
    }

    const int m0 = blockIdx.y * 128;
    const int n0 = blockIdx.x * 128;
    const int tx = tid & 15;        // n microtile
    const int ty = tid >> 4;        // m microtile

    const int aRow = tid >> 2;
    const int aK   = (tid & 3) * 4;
    const int bRow = tid >> 5;
    const int bC   = (tid & 31) * 4;

    unsigned long long acc2[8][4];
#pragma unroll
    for (int i = 0; i < 8; i++)
#pragma unroll
        for (int j = 0; j < 4; j++) acc2[i][j] = 0ull;

    for (int k0 = 0; k0 < II; k0 += 16) {
#pragma unroll
        for (int it = 0; it < 2; it++) {
            int row = aRow + it * 64;
            float4 v = *(const float4*)&A[(size_t)(m0 + row) * II + k0 + aK];
            As[aK + 0][row] = v.x;
            As[aK + 1][row] = v.y;
            As[aK + 2][row] = v.z;
            As[aK + 3][row] = v.w;
        }
#pragma unroll
        for (int it = 0; it < 2; it++) {
            int rr = bRow + it * 8;
            *(float4*)&Bs[rr][bC] =
                *(const float4*)&W[(size_t)(k0 + rr) * HH + n0 + bC];
        }
        __syncthreads();
#pragma unroll
        for (int kk = 0; kk < 16; kk++) {
            float a[8];
            *(float4*)&a[0] = *(const float4*)&As[kk][ty * 8];
            *(float4*)&a[4] = *(const float4*)&As[kk][ty * 8 + 4];
            double2 bx = *(const double2*)&Bs[kk][tx * 8];
            double2 by = *(const double2*)&Bs[kk][tx * 8 + 4];
            unsigned long long b01 = dl(bx.x), b23 = dl(bx.y);
            unsigned long long b45 = dl(by.x), b67 = dl(by.y);
#pragma unroll
            for (int i = 0; i < 8; i++) {
                unsigned long long ap = pack2(a[i]);
                fma2(acc2[i][0], ap, b01);
                fma2(acc2[i][1], ap, b23);
                fma2(acc2[i][2], ap, b45);
                fma2(acc2[i][3], ap, b67);
            }
        }
        __syncthreads();
    }

#pragma unroll
    for (int i = 0; i < 8; i++) {
        int row = m0 + ty * 8 + i;
        float c[8];
#pragma unroll
        for (int j = 0; j < 4; j++) unpack2(acc2[i][j], c[2 * j], c[2 * j + 1]);
#pragma unroll
        for (int j = 0; j < 8; j++) c[j] += bias[n0 + tx * 8 + j];
        *(float4*)&C[(size_t)row * HH + n0 + tx * 8]     = *(float4*)&c[0];
        *(float4*)&C[(size_t)row * HH + n0 + tx * 8 + 4] = *(float4*)&c[4];
    }
}

// ---------------------------------------------------------------------------
// Phase 2: persistent recurrence. rg-scoped counter barrier + bulk coalesced
// h staging + 4x4xks8 register blocking (1 W-LDS feeds 8 FFMA2-halves;
// LDS:FFMA2 = 1:4).
//
// CTA (rg, cgp): rows rg*16..+16, cols cgp*32..+32. SMEM: W tile 1024x32
// k-major (128 KB, resident all 512 steps), h tile 16x1024 with an 8-float
// pad per 4-row group (64.1 KB), pbuf 8x16x44 (22 KB). 219 KB -> 1 CTA/SM.
//
// Threads: tid = ks(3b)|rbl(2b)|cg(3b). Thread owns rows rbl*4..+4, cols
// cg*4..+4, k-range ks*128..+128. Per k: 1 W-LDS.128 (4 cols, 8 distinct
// per warp = all 32 banks) + h float4 per row (4 distinct rows per warp,
// pad gives bank shifts {0,8,16,24}); 8 FFMA2. Partials -> pbuf, 8-way ks
// reduce; every thread finishes 2 outputs (tanh + store to out and ring).
// ---------------------------------------------------------------------------
__global__ __launch_bounds__(256, 1) void rnn_recur(
    const float* __restrict__ Whh, float* __restrict__ out) {
    extern __shared__ __align__(16) float smem_dyn[];
    float* ws   = smem_dyn;              // [1024][32] k-major
    float* hs   = ws + WS_FLOATS;        // 16 rows, pad 8 floats per 4 rows
    float* pbuf = hs + HS_FLOATS;        // [8][16][44]

    const int tid = threadIdx.x;
    const int cg  = tid & 7;
    const int rbl = (tid >> 3) & 3;
    const int ks  = tid >> 5;
    const int r0  = rbl * 4;

    const int rg      = blockIdx.x >> 5;
    const int rowbase = rg * RG_ROWS;
    const int colbase = (blockIdx.x & 31) * CG_COLS;
    unsigned* cnt     = &g_cnt[rg * 64];

    // --- Prologue: load W tile (1024 x 32) into smem k-major, once. ---
    {
        const float4* wsrc0 = (const float4*)(Whh + colbase);
        float4* wdst = (float4*)ws;
#pragma unroll
        for (int i = 0; i < 32; i++) {
            int idx4 = tid + i * 256;           // 8192 float4 total
            int k  = idx4 >> 3;                 // 8 float4 per W row
            int c4 = idx4 & 7;
            wdst[idx4] = wsrc0[(size_t)k * (HH / 4) + c4];
        }
    }
    __syncthreads();

    // h base for this thread: 4-row group rbl (pad 8 floats per group).
    const float* hbase = hs + (size_t)rbl * (4 * 1024 + 8) + ks * 128;
    const float* wk0   = ws + (size_t)(ks * 128) * CG_COLS + cg * 4;

    // Epilogue mapping: thread finishes outputs idx = 2*tid, 2*tid+1.
    const int er = (2 * tid) >> 5;          // local row 0..15
    const int ec = (2 * tid) & 31;          // local col (even)

    for (int t = 1; t <= TT; t++) {
        // Prefetch x_proj operand (t-indexed only — legal before the spin;
        // hides its L2 latency behind barrier detect).
        const size_t oidx =
            ((size_t)(rowbase + er) * TT + (t - 1)) * HH + colbase + ec;
        float2 xp = *(const float2*)&out[oidx];

        // --- Wait: all 32 rg producers have published step t-1. ---
        if (t > 1) {
            if (tid == 0) {
                const unsigned want = 32u * (unsigned)(t - 1);
                unsigned v;
                do {
                    asm volatile("ld.acquire.gpu.global.b32 %0, [%1];"
                                 : "=r"(v) : "l"(cnt) : "memory");
                } while (v < want);
            }
            __syncthreads();
        }

        // --- Stage h tile (16 x 1024) into group-padded smem: coalesced. ---
        {
            const float4* src = (const float4*)(&g_h[(t - 1) & 1][rowbase * HH]);
            float4* dst = (float4*)hs;
#pragma unroll
            for (int i = 0; i < 16; i++) {
                int idx4 = tid + i * 256;       // 4096 float4 total
                int row  = idx4 >> 8;           // 256 float4 per h row
                dst[idx4 + (row >> 2) * 2] = __ldcg(&src[idx4]);
            }
        }
        __syncthreads();

        // --- Inner: 4 rows x 4 cols x 128 k, all operands from smem. ---
        unsigned long long acc[4][2];
#pragma unroll
        for (int i = 0; i < 4; i++) { acc[i][0] = 0ull; acc[i][1] = 0ull; }

#pragma unroll 4
        for (int k = 0; k < 128; k += 4) {
            float4 h0 = *(const float4*)(hbase + 0 * 1024 + k);
            float4 h1 = *(const float4*)(hbase + 1 * 1024 + k);
            float4 h2 = *(const float4*)(hbase + 2 * 1024 + k);
            float4 h3 = *(const float4*)(hbase + 3 * 1024 + k);
            const float* f0 = &h0.x;
            const float* f1 = &h1.x;
            const float* f2 = &h2.x;
            const float* f3 = &h3.x;
#pragma unroll
            for (int j = 0; j < 4; j++) {
                ulonglong2 w = *(const ulonglong2*)(wk0 + (size_t)(k + j) * CG_COLS);
                unsigned long long hp;
                hp = pack2(f0[j]); fma2(acc[0][0], hp, w.x); fma2(acc[0][1], hp, w.y);
                hp = pack2(f1[j]); fma2(acc[1][0], hp, w.x); fma2(acc[1][1], hp, w.y);
                hp = pack2(f2[j]); fma2(acc[2][0], hp, w.x); fma2(acc[2][1], hp, w.y);
                hp = pack2(f3[j]); fma2(acc[3][0], hp, w.x); fma2(acc[3][1], hp, w.y);
            }
        }

        // --- Partials to smem: pbuf[ks][row][cg*4..+3]. ---
#pragma unroll
        for (int i = 0; i < 4; i++) {
            ulonglong2* p = (ulonglong2*)(pbuf +
                ((size_t)ks * PB_PLANE + (size_t)(r0 + i) * PB_STRIDE + cg * 4));
            *p = make_ulonglong2(acc[i][0], acc[i][1]);
        }
        __syncthreads();

        // --- ks-reduce (8 planes) + tanh + store: 2 outputs per thread. ---
        {
            const float* pb = pbuf + (size_t)er * PB_STRIDE + ec;
            float sx = xp.x, sy = xp.y;
#pragma unroll
            for (int p = 0; p < KS; p++) {
                float2 s = *(const float2*)(pb + (size_t)p * PB_PLANE);
                sx += s.x;
                sy += s.y;
            }
            float2 hv;
            hv.x = tanhf(sx);
            hv.y = tanhf(sy);
            *(float2*)&out[oidx] = hv;
            *(float2*)&g_h[t & 1][(size_t)(rowbase + er) * HH + colbase + ec] = hv;
        }
        __syncthreads();

        // --- Publish: arrive on the rg counter (RED, no return). ---
        if (tid == 0) {
            __threadfence();
            asm volatile("red.release.gpu.global.add.u32 [%0], %1;"
                         :: "l"(cnt), "r"(1u) : "memory");
        }
    }
}

// ---------------------------------------------------------------------------
// inputs: d_in[0]=inputs (B,T,I) f32, d_in[1]=h_prev (B,H) f32,
//         d_in[2]=W_xh (I,H) f32, d_in[3]=W_hh (H,H) f32, d_in[4]=b_h (H) f32
// out: (B,T,H) f32
// ---------------------------------------------------------------------------
extern "C" void kernel_launch(void* const* d_in, const int* in_sizes, int n_in,
                              void* d_out, int out_size) {
    const float* x      = (const float*)d_in[0];
    const float* h_prev = (const float*)d_in[1];
    const float* W_xh   = (const float*)d_in[2];
    const float* W_hh   = (const float*)d_in[3];
    const float* b_h    = (const float*)d_in[4];
    float* out = (float*)d_out;

    (void)in_sizes; (void)n_in; (void)out_size;

    // 128 KB (W) + 64.1 KB (h) + 22 KB (pbuf) = 219264 B -> 1 CTA/SM.
    const int smem_bytes = (WS_FLOATS + HS_FLOATS + PB_FLOATS) * 4;
    cudaFuncSetAttribute(rnn_recur, cudaFuncAttributeMaxDynamicSharedMemorySize,
                         smem_bytes);

    xproj_gemm<<<dim3(HH / 128, (BB * TT) / 128), 256>>>(x, W_xh, b_h, h_prev, out);
    rnn_recur<<<128, 256, smem_bytes>>>(W_hh, out);
}

// round 15
// speedup vs baseline: 1.2732x; 1.2732x over previous
#include <cuda_runtime.h>

#define BB 64
#define TT 512
#define II 512
#define HH 1024

// Recurrence tiling: 128 CTAs = 4 row-groups (16 rows) x 32 col-groups (32 cols).
#define RG_ROWS 16
#define CG_COLS 32
#define KS 8                        // k-split ways
#define HS_STRIDE 1028              // padded h row stride: rows-in-warp 2 apart ->
                                    // bank shifts {0,8,16,24}; 16B-multiple.
#define PB_STRIDE 44                // pbuf row stride (floats); 16B-multiple
#define PB_PLANE (RG_ROWS * PB_STRIDE)

#define WS_FLOATS (1024 * CG_COLS)          // 32768
#define HS_FLOATS (RG_ROWS * HS_STRIDE)     // 16448
#define PB_FLOATS (KS * PB_PLANE)           // 5632

// h double buffer (ring) + per-row-group monotone barrier counters.
__device__ float g_h[2][BB * HH];
__device__ unsigned g_cnt[4 * 64];

// ---------------------------------------------------------------------------
// Packed f32x2 helpers (Blackwell FFMA2 — only reachable via PTX fma.rn.f32x2).
// ---------------------------------------------------------------------------
__device__ __forceinline__ unsigned long long pack2(float v) {
    unsigned long long r;
    asm("mov.b64 %0, {%1, %1};" : "=l"(r) : "f"(v));
    return r;
}
__device__ __forceinline__ void fma2(unsigned long long& d,
                                     unsigned long long a,
                                     unsigned long long b) {
    asm("fma.rn.f32x2 %0, %1, %2, %0;" : "+l"(d) : "l"(a), "l"(b));
}
__device__ __forceinline__ void unpack2(unsigned long long v, float& lo, float& hi) {
    asm("mov.b64 {%0, %1}, %2;" : "=f"(lo), "=f"(hi) : "l"(v));
}
__device__ __forceinline__ unsigned long long dl(double d) {
    return __double_as_longlong(d);
}

// ---------------------------------------------------------------------------
// Phase 1: x_proj = inputs(32768x512) @ W_xh(512x1024) + b  -> written to out.
// 128x128 tile, 8x8 microtile, BK=16, packed FFMA2 inner product.
// CTA (0,0) additionally resets the rg barrier counters and stages h_prev
// into ring[0] (stream order guarantees visibility to rnn_recur).
// ---------------------------------------------------------------------------
__global__ __launch_bounds__(256, 2) void xproj_gemm(
    const float* __restrict__ A, const float* __restrict__ W,
    const float* __restrict__ bias, const float* __restrict__ h_prev,
    float* __restrict__ C) {
    __shared__ __align__(16) float As[16][128];   // As[k][m]
    __shared__ __align__(16) float Bs[16][128];   // Bs[k][n]

    const int tid = threadIdx.x;

    // Merged init (one CTA): counters = 0, ring[0] = h_prev.
    if (blockIdx.x == 0 && blockIdx.y == 0) {
        if (tid < 4) g_cnt[tid * 64] = 0u;
        const float4* hp4 = (const float4*)h_prev;
        float4* r0 = (float4*)g_h[0];
#pragma unroll
        for (int i = 0; i < 64; i++)
            r0[tid + i * 256] = hp4[tid + i * 256];
    }

    const int m0 = blockIdx.y * 128;
    const int n0 = blockIdx.x * 128;
    const int tx = tid & 15;        // n microtile
    const int ty = tid >> 4;        // m microtile

    const int aRow = tid >> 2;
    const int aK   = (tid & 3) * 4;
    const int bRow = tid >> 5;
    const int bC   = (tid & 31) * 4;

    unsigned long long acc2[8][4];
#pragma unroll
    for (int i = 0; i < 8; i++)
#pragma unroll
        for (int j = 0; j < 4; j++) acc2[i][j] = 0ull;

    for (int k0 = 0; k0 < II; k0 += 16) {
#pragma unroll
        for (int it = 0; it < 2; it++) {
            int row = aRow + it * 64;
            float4 v = *(const float4*)&A[(size_t)(m0 + row) * II + k0 + aK];
            As[aK + 0][row] = v.x;
            As[aK + 1][row] = v.y;
            As[aK + 2][row] = v.z;
            As[aK + 3][row] = v.w;
        }
#pragma unroll
        for (int it = 0; it < 2; it++) {
            int rr = bRow + it * 8;
            *(float4*)&Bs[rr][bC] =
                *(const float4*)&W[(size_t)(k0 + rr) * HH + n0 + bC];
        }
        __syncthreads();
#pragma unroll
        for (int kk = 0; kk < 16; kk++) {
            float a[8];
            *(float4*)&a[0] = *(const float4*)&As[kk][ty * 8];
            *(float4*)&a[4] = *(const float4*)&As[kk][ty * 8 + 4];
            double2 bx = *(const double2*)&Bs[kk][tx * 8];
            double2 by = *(const double2*)&Bs[kk][tx * 8 + 4];
            unsigned long long b01 = dl(bx.x), b23 = dl(bx.y);
            unsigned long long b45 = dl(by.x), b67 = dl(by.y);
#pragma unroll
            for (int i = 0; i < 8; i++) {
                unsigned long long ap = pack2(a[i]);
                fma2(acc2[i][0], ap, b01);
                fma2(acc2[i][1], ap, b23);
                fma2(acc2[i][2], ap, b45);
                fma2(acc2[i][3], ap, b67);
            }
        }
        __syncthreads();
    }

#pragma unroll
    for (int i = 0; i < 8; i++) {
        int row = m0 + ty * 8 + i;
        float c[8];
#pragma unroll
        for (int j = 0; j < 4; j++) unpack2(acc2[i][j], c[2 * j], c[2 * j + 1]);
#pragma unroll
        for (int j = 0; j < 8; j++) c[j] += bias[n0 + tx * 8 + j];
        *(float4*)&C[(size_t)row * HH + n0 + tx * 8]     = *(float4*)&c[0];
        *(float4*)&C[(size_t)row * HH + n0 + tx * 8 + 4] = *(float4*)&c[4];
    }
}

// ---------------------------------------------------------------------------
// Phase 2: persistent recurrence — R13's best-known tiling (2 rows x 4 cols
// per thread, conflict-free banking) at 512 THREADS (16 warps, 4/SMSP) so
// LDS-return latency is hidden by warp parallelism (R13/R14 showed issue
// stuck at ~22-25% with only 8 warps).
//
// CTA (rg, cgp): rows rg*16..+16, cols cgp*32..+32. SMEM: W tile 1024x32
// k-major (128 KB, resident all 512 steps), h tile 16x1028 (64.3 KB, staged
// per step), pbuf 8x16x44 (22 KB). 219 KB -> 1 CTA/SM.
//
// Threads (512): tid = ks(3b)|rbl(3b)|cg(3b). Thread owns rows {rbl*2,
// rbl*2+1}, cols cg*4..+4, k-range ks*128..+128. Per 4k: 2 h LDS.128 +
// 4 W LDS.128 feed 16 FFMA2. Partials -> pbuf, 8-way ks reduce; each
// thread finishes exactly 1 output (tanh + store out + ring), coalesced.
// ---------------------------------------------------------------------------
__global__ __launch_bounds__(512, 1) void rnn_recur(
    const float* __restrict__ Whh, float* __restrict__ out) {
    extern __shared__ __align__(16) float smem_dyn[];
    float* ws   = smem_dyn;              // [1024][32] k-major
    float* hs   = ws + WS_FLOATS;        // [16][1028]
    float* pbuf = hs + HS_FLOATS;        // [8][16][44]

    const int tid = threadIdx.x;
    const int cg  = tid & 7;
    const int rbl = (tid >> 3) & 7;
    const int ks  = tid >> 6;
    const int r0  = rbl * 2;

    const int rg      = blockIdx.x >> 5;
    const int rowbase = rg * RG_ROWS;
    const int colbase = (blockIdx.x & 31) * CG_COLS;
    unsigned* cnt     = &g_cnt[rg * 64];

    // --- Prologue: load W tile (1024 x 32) into smem k-major, once. ---
    {
        const float4* wsrc0 = (const float4*)(Whh + colbase);
        float4* wdst = (float4*)ws;
#pragma unroll
        for (int i = 0; i < 16; i++) {
            int idx4 = tid + i * 512;           // 8192 float4 total
            int k  = idx4 >> 3;                 // 8 float4 per W row
            int c4 = idx4 & 7;
            wdst[idx4] = wsrc0[(size_t)k * (HH / 4) + c4];
        }
    }
    __syncthreads();

    const float* hrow0 = hs + (size_t)r0 * HS_STRIDE + ks * 128;
    const float* wk0   = ws + (size_t)(ks * 128) * CG_COLS + cg * 4;

    // Epilogue mapping: thread finishes output idx = tid (er = warp id).
    const int er = tid >> 5;                // local row 0..15
    const int ec = tid & 31;                // local col

    for (int t = 1; t <= TT; t++) {
        // Prefetch x_proj operand (t-indexed only — hidden behind the spin).
        const size_t oidx =
            ((size_t)(rowbase + er) * TT + (t - 1)) * HH + colbase + ec;
        float xp = out[oidx];

        // --- Wait: all 32 rg producers have published step t-1. ---
        if (t > 1) {
            if (tid == 0) {
                const unsigned want = 32u * (unsigned)(t - 1);
                unsigned v;
                do {
                    asm volatile("ld.acquire.gpu.global.b32 %0, [%1];"
                                 : "=r"(v) : "l"(cnt) : "memory");
                } while (v < want);
            }
            __syncthreads();
        }

        // --- Stage h tile (16 x 1024) into padded smem: coalesced, MLP=8. ---
        {
            const float4* src = (const float4*)(&g_h[(t - 1) & 1][rowbase * HH]);
            float4* dst = (float4*)hs;
#pragma unroll
            for (int i = 0; i < 8; i++) {
                int idx4 = tid + i * 512;       // 4096 float4 total
                int row  = idx4 >> 8;           // 256 float4 per h row
                int k4   = idx4 & 255;
                dst[row * (HS_STRIDE / 4) + k4] = __ldcg(&src[idx4]);
            }
        }
        __syncthreads();

        // --- Inner: 2 rows x 4 cols x 128 k, all operands from smem. ---
        unsigned long long a00 = 0ull, a01 = 0ull, a10 = 0ull, a11 = 0ull;
#pragma unroll 4
        for (int k = 0; k < 128; k += 4) {
            float4 hA = *(const float4*)(hrow0 + k);
            float4 hB = *(const float4*)(hrow0 + HS_STRIDE + k);
            const float* fA = &hA.x;
            const float* fB = &hB.x;
#pragma unroll
            for (int j = 0; j < 4; j++) {
                ulonglong2 w = *(const ulonglong2*)(wk0 + (size_t)(k + j) * CG_COLS);
                unsigned long long hp;
                hp = pack2(fA[j]);
                fma2(a00, hp, w.x);
                fma2(a01, hp, w.y);
                hp = pack2(fB[j]);
                fma2(a10, hp, w.x);
                fma2(a11, hp, w.y);
            }
        }

        // --- Partials to smem: pbuf[ks][row][cg*4..+3]. ---
        {
            ulonglong2* p0 = (ulonglong2*)(pbuf +
                ((size_t)ks * PB_PLANE + (size_t)r0 * PB_STRIDE + cg * 4));
            ulonglong2* p1 = (ulonglong2*)(pbuf +
                ((size_t)ks * PB_PLANE + (size_t)(r0 + 1) * PB_STRIDE + cg * 4));
            *p0 = make_ulonglong2(a00, a01);
            *p1 = make_ulonglong2(a10, a11);
        }
        __syncthreads();

        // --- ks-reduce (8 planes) + tanh + store: 1 output per thread.
        //     er = warp id -> lanes span banks 0..31: conflict-free. ---
        {
            const float* pb = pbuf + (size_t)er * PB_STRIDE + ec;
            float s = xp;
#pragma unroll
            for (int p = 0; p < KS; p++) s += pb[(size_t)p * PB_PLANE];
            float hv = tanhf(s);
            out[oidx] = hv;
            g_h[t & 1][(size_t)(rowbase + er) * HH + colbase + ec] = hv;
        }
        __syncthreads();

        // --- Publish: arrive on the rg counter (RED, no return). ---
        if (tid == 0) {
            __threadfence();
            asm volatile("red.release.gpu.global.add.u32 [%0], %1;"
                         :: "l"(cnt), "r"(1u) : "memory");
        }
    }
}

// ---------------------------------------------------------------------------
// inputs: d_in[0]=inputs (B,T,I) f32, d_in[1]=h_prev (B,H) f32,
//         d_in[2]=W_xh (I,H) f32, d_in[3]=W_hh (H,H) f32, d_in[4]=b_h (H) f32
// out: (B,T,H) f32
// ---------------------------------------------------------------------------
extern "C" void kernel_launch(void* const* d_in, const int* in_sizes, int n_in,
                              void* d_out, int out_size) {
    const float* x      = (const float*)d_in[0];
    const float* h_prev = (const float*)d_in[1];
    const float* W_xh   = (const float*)d_in[2];
    const float* W_hh   = (const float*)d_in[3];
    const float* b_h    = (const float*)d_in[4];
    float* out = (float*)d_out;

    (void)in_sizes; (void)n_in; (void)out_size;

    // 128 KB (W) + 64.3 KB (h) + 22 KB (pbuf) = 219392 B -> 1 CTA/SM.
    const int smem_bytes = (WS_FLOATS + HS_FLOATS + PB_FLOATS) * 4;
    cudaFuncSetAttribute(rnn_recur, cudaFuncAttributeMaxDynamicSharedMemorySize,
                         smem_bytes);

    xproj_gemm<<<dim3(HH / 128, (BB * TT) / 128), 256>>>(x, W_xh, b_h, h_prev, out);
    rnn_recur<<<128, 512, smem_bytes>>>(W_hh, out);
}

// round 16
// speedup vs baseline: 1.3870x; 1.0893x over previous
#include <cuda_runtime.h>

#define BB 64
#define TT 512
#define II 512
#define HH 1024

// Recurrence tiling: 128 CTAs = 4 row-groups (16 rows) x 32 col-groups (32 cols).
#define RG_ROWS 16
#define CG_COLS 32
#define HS_STRIDE 20                 // transposed h: hs[k][16 rows + 4 pad]
#define PB_STRIDE 520                // pbuf plane stride: 16 rows x 32 + 8 pad

#define WS_FLOATS (1024 * CG_COLS)   // 32768 (128 KB)
#define HS_FLOATS (1024 * HS_STRIDE) // 20480 (80 KB)
#define PB_FLOATS (8 * PB_STRIDE)    // 4160  (16.6 KB)

// h double buffer (ring) + per-row-group monotone barrier counters.
__device__ float g_h[2][BB * HH];
__device__ unsigned g_cnt[4 * 64];

// ---------------------------------------------------------------------------
// Packed f32x2 helpers (Blackwell FFMA2 — only reachable via PTX fma.rn.f32x2).
// ---------------------------------------------------------------------------
__device__ __forceinline__ unsigned long long pack2(float v) {
    unsigned long long r;
    asm("mov.b64 %0, {%1, %1};" : "=l"(r) : "f"(v));
    return r;
}
__device__ __forceinline__ void fma2(unsigned long long& d,
                                     unsigned long long a,
                                     unsigned long long b) {
    asm("fma.rn.f32x2 %0, %1, %2, %0;" : "+l"(d) : "l"(a), "l"(b));
}
__device__ __forceinline__ void add2(unsigned long long& d,
                                     unsigned long long a) {
    asm("add.rn.f32x2 %0, %0, %1;" : "+l"(d) : "l"(a));
}
__device__ __forceinline__ void unpack2(unsigned long long v, float& lo, float& hi) {
    asm("mov.b64 {%0, %1}, %2;" : "=f"(lo), "=f"(hi) : "l"(v));
}
__device__ __forceinline__ unsigned long long dl(double d) {
    return __double_as_longlong(d);
}

// ---------------------------------------------------------------------------
// Phase 1: x_proj = inputs(32768x512) @ W_xh(512x1024) + b  -> written to out.
// 128x128 tile, 8x8 microtile, BK=16, packed FFMA2 inner product.
// CTA (0,0) additionally resets the rg barrier counters and stages h_prev
// into ring[0] (stream order guarantees visibility to rnn_recur).
// ---------------------------------------------------------------------------
__global__ __launch_bounds__(256, 2) void xproj_gemm(
    const float* __restrict__ A, const float* __restrict__ W,
    const float* __restrict__ bias, const float* __restrict__ h_prev,
    float* __restrict__ C) {
    __shared__ __align__(16) float As[16][128];   // As[k][m]
    __shared__ __align__(16) float Bs[16][128];   // Bs[k][n]

    const int tid = threadIdx.x;

    // Merged init (one CTA): counters = 0, ring[0] = h_prev.
    if (blockIdx.x == 0 && blockIdx.y == 0) {
        if (tid < 4) g_cnt[tid * 64] = 0u;
        const float4* hp4 = (const float4*)h_prev;
        float4* r0 = (float4*)g_h[0];
#pragma unroll
        for (int i = 0; i < 64; i++)
            r0[tid + i * 256] = hp4[tid + i * 256];
    }

    const int m0 = blockIdx.y * 128;
    const int n0 = blockIdx.x * 128;
    const int tx = tid & 15;        // n microtile
    const int ty = tid >> 4;        // m microtile

    const int aRow = tid >> 2;
    const int aK   = (tid & 3) * 4;
    const int bRow = tid >> 5;
    const int bC   = (tid & 31) * 4;

    unsigned long long acc2[8][4];
#pragma unroll
    for (int i = 0; i < 8; i++)
#pragma unroll
        for (int j = 0; j < 4; j++) acc2[i][j] = 0ull;

    for (int k0 = 0; k0 < II; k0 += 16) {
#pragma unroll
        for (int it = 0; it < 2; it++) {
            int row = aRow + it * 64;
            float4 v = *(const float4*)&A[(size_t)(m0 + row) * II + k0 + aK];
            As[aK + 0][row] = v.x;
            As[aK + 1][row] = v.y;
            As[aK + 2][row] = v.z;
            As[aK + 3][row] = v.w;
        }
#pragma unroll
        for (int it = 0; it < 2; it++) {
            int rr = bRow + it * 8;
            *(float4*)&Bs[rr][bC] =
                *(const float4*)&W[(size_t)(k0 + rr) * HH + n0 + bC];
        }
        __syncthreads();
#pragma unroll
        for (int kk = 0; kk < 16; kk++) {
            float a[8];
            *(float4*)&a[0] = *(const float4*)&As[kk][ty * 8];
            *(float4*)&a[4] = *(const float4*)&As[kk][ty * 8 + 4];
            double2 bx = *(const double2*)&Bs[kk][tx * 8];
            double2 by = *(const double2*)&Bs[kk][tx * 8 + 4];
            unsigned long long b01 = dl(bx.x), b23 = dl(bx.y);
            unsigned long long b45 = dl(by.x), b67 = dl(by.y);
#pragma unroll
            for (int i = 0; i < 8; i++) {
                unsigned long long ap = pack2(a[i]);
                fma2(acc2[i][0], ap, b01);
                fma2(acc2[i][1], ap, b23);
                fma2(acc2[i][2], ap, b45);
                fma2(acc2[i][3], ap, b67);
            }
        }
        __syncthreads();
    }

#pragma unroll
    for (int i = 0; i < 8; i++) {
        int row = m0 + ty * 8 + i;
        float c[8];
#pragma unroll
        for (int j = 0; j < 4; j++) unpack2(acc2[i][j], c[2 * j], c[2 * j + 1]);
#pragma unroll
        for (int j = 0; j < 8; j++) c[j] += bias[n0 + tx * 8 + j];
        *(float4*)&C[(size_t)row * HH + n0 + tx * 8]     = *(float4*)&c[0];
        *(float4*)&C[(size_t)row * HH + n0 + tx * 8 + 4] = *(float4*)&c[4];
    }
}

// ---------------------------------------------------------------------------
// Phase 2: persistent recurrence — crossbar-minimal tiling.
//
// CTA (rg, cgp): rows rg*16..+16, cols cgp*32..+32. SMEM: W [1024][32]
// k-major (128 KB, resident), h TRANSPOSED hs[k][16 rows] stride 20 (80 KB,
// staged per step), pbuf 8 planes x (16x32+8) (16.6 KB). 229.6 KB, 1 CTA/SM.
//
// Threads (256): tid = ks(4b)|rbl(2b)|cg(2b). Thread: rows rbl*4..+4, cols
// cg*8..+8, k-range ks*64..+64. Warp = ks pair {2w,2w+1}; within a warp the
// 4 rbl lanes share W addresses -> broadcast dedup: W is read from smem
// EXACTLY ONCE per step (was 8x). Per k per thread: 2 W-LDS.128 (ks-parity
// +-4-word offset -> even/odd ks hit disjoint bank quads, 1 wavefront/inst)
// + 1 transposed-h LDS.128 (4 rows at k) -> 16 FFMA2.
// Partials: 16 ks-planes folded 16->8 in smem, then 8-plane reduce; each
// thread finishes 2 outputs (tanh + store out + ring).
// ---------------------------------------------------------------------------
__global__ __launch_bounds__(256, 1) void rnn_recur(
    const float* __restrict__ Whh, float* __restrict__ out) {
    extern __shared__ __align__(16) float smem_dyn[];
    float* ws   = smem_dyn;              // [1024][32] k-major
    float* hs   = ws + WS_FLOATS;        // [1024][20] transposed h
    float* pbuf = hs + HS_FLOATS;        // [8][520]

    const int tid = threadIdx.x;
    const int cg  = tid & 3;
    const int rbl = (tid >> 2) & 3;
    const int ks  = tid >> 4;
    const int r0  = rbl * 4;
    const int swz = (ks & 1) * 4;        // ks-parity bank offset (cols)
    const int colA = cg * 8 + swz;       // 4 cols covered by first W float4
    const int colB = cg * 8 + (swz ^ 4); // 4 cols covered by second

    const int rg      = blockIdx.x >> 5;
    const int rowbase = rg * RG_ROWS;
    const int colbase = (blockIdx.x & 31) * CG_COLS;
    unsigned* cnt     = &g_cnt[rg * 64];

    // --- Prologue: load W tile (1024 x 32) into smem k-major, once. ---
    {
        const float4* wsrc0 = (const float4*)(Whh + colbase);
        float4* wdst = (float4*)ws;
#pragma unroll
        for (int i = 0; i < 32; i++) {
            int idx4 = tid + i * 256;           // 8192 float4 total
            int k  = idx4 >> 3;                 // 8 float4 per W row
            int c4 = idx4 & 7;
            wdst[idx4] = wsrc0[(size_t)k * (HH / 4) + c4];
        }
    }
    __syncthreads();

    const float* wA = ws + (size_t)(ks * 64) * CG_COLS + colA;
    const float* wB = ws + (size_t)(ks * 64) * CG_COLS + colB;
    const float* hk = hs + (size_t)(ks * 64) * HS_STRIDE + r0;

    // Epilogue mapping: thread finishes 2 outputs (row er, cols ec2, ec2+1).
    const int er  = tid >> 4;               // local row 0..15
    const int ec2 = (tid & 15) * 2;         // local col (even)

    for (int t = 1; t <= TT; t++) {
        // Prefetch x_proj operand (t-indexed only — hidden behind the spin).
        const size_t oidx =
            ((size_t)(rowbase + er) * TT + (t - 1)) * HH + colbase + ec2;
        float2 xp = *(const float2*)&out[oidx];

        // --- Wait: all 32 rg producers have published step t-1. ---
        if (t > 1) {
            if (tid == 0) {
                const unsigned want = 32u * (unsigned)(t - 1);
                unsigned v;
                do {
                    asm volatile("ld.acquire.gpu.global.b32 %0, [%1];"
                                 : "=r"(v) : "l"(cnt) : "memory");
                } while (v < want);
            }
            __syncthreads();
        }

        // --- Stage h tile TRANSPOSED: hs[k][row] = h[row][k]. Coalesced
        //     LDG (4 rows x 128B runs per warp); STS.32 4-way wavefronts. ---
        {
            const float4* src = (const float4*)(&g_h[(t - 1) & 1][rowbase * HH]);
#pragma unroll
            for (int i = 0; i < 16; i++) {
                int idx = tid + i * 256;        // 0..4095
                int k4p = idx & 7;
                int rlo = (idx >> 3) & 3;
                int k4h = (idx >> 5) & 31;
                int rhi = idx >> 10;
                int k4  = (k4h << 3) | k4p;     // 0..255
                int row = (rhi << 2) | rlo;     // 0..15
                float4 v = __ldcg(&src[row * 256 + k4]);
                float* d = hs + (size_t)(k4 * 4) * HS_STRIDE + row;
                d[0 * HS_STRIDE] = v.x;
                d[1 * HS_STRIDE] = v.y;
                d[2 * HS_STRIDE] = v.z;
                d[3 * HS_STRIDE] = v.w;
            }
        }
        __syncthreads();

        // --- Inner: 4 rows x 8 cols x 64 k. W read once per step (bcast). ---
        unsigned long long acc[4][4];
#pragma unroll
        for (int i = 0; i < 4; i++)
#pragma unroll
            for (int p = 0; p < 4; p++) acc[i][p] = 0ull;

#pragma unroll 4
        for (int kk = 0; kk < 64; kk++) {
            ulonglong2 a = *(const ulonglong2*)(wA + (size_t)kk * CG_COLS);
            ulonglong2 b = *(const ulonglong2*)(wB + (size_t)kk * CG_COLS);
            float4 hv = *(const float4*)(hk + (size_t)kk * HS_STRIDE);
            unsigned long long hp;
            hp = pack2(hv.x);
            fma2(acc[0][0], hp, a.x); fma2(acc[0][1], hp, a.y);
            fma2(acc[0][2], hp, b.x); fma2(acc[0][3], hp, b.y);
            hp = pack2(hv.y);
            fma2(acc[1][0], hp, a.x); fma2(acc[1][1], hp, a.y);
            fma2(acc[1][2], hp, b.x); fma2(acc[1][3], hp, b.y);
            hp = pack2(hv.z);
            fma2(acc[2][0], hp, a.x); fma2(acc[2][1], hp, a.y);
            fma2(acc[2][2], hp, b.x); fma2(acc[2][3], hp, b.y);
            hp = pack2(hv.w);
            fma2(acc[3][0], hp, a.x); fma2(acc[3][1], hp, a.y);
            fma2(acc[3][2], hp, b.x); fma2(acc[3][3], hp, b.y);
        }

        // --- Fold 16 ks-planes into 8: ks<8 write, then ks>=8 add. ---
        float* plane = pbuf + (size_t)(ks & 7) * PB_STRIDE;
        if (ks < 8) {
#pragma unroll
            for (int i = 0; i < 4; i++) {
                *(ulonglong2*)(plane + (r0 + i) * 32 + colA) =
                    make_ulonglong2(acc[i][0], acc[i][1]);
                *(ulonglong2*)(plane + (r0 + i) * 32 + colB) =
                    make_ulonglong2(acc[i][2], acc[i][3]);
            }
        }
        __syncthreads();
        if (ks >= 8) {
#pragma unroll
            for (int i = 0; i < 4; i++) {
                ulonglong2* pA = (ulonglong2*)(plane + (r0 + i) * 32 + colA);
                ulonglong2* pB = (ulonglong2*)(plane + (r0 + i) * 32 + colB);
                ulonglong2 vA = *pA, vB = *pB;
                add2(vA.x, acc[i][0]); add2(vA.y, acc[i][1]);
                add2(vB.x, acc[i][2]); add2(vB.y, acc[i][3]);
                *pA = vA; *pB = vB;
            }
        }
        __syncthreads();

        // --- 8-plane reduce + tanh + store: 2 outputs per thread. ---
        {
            const float* pb = pbuf + (size_t)er * 32 + ec2;
            float sx = xp.x, sy = xp.y;
#pragma unroll
            for (int p = 0; p < 8; p++) {
                float2 s = *(const float2*)(pb + (size_t)p * PB_STRIDE);
                sx += s.x;
                sy += s.y;
            }
            float2 hv;
            hv.x = tanhf(sx);
            hv.y = tanhf(sy);
            *(float2*)&out[oidx] = hv;
            *(float2*)&g_h[t & 1][(size_t)(rowbase + er) * HH + colbase + ec2] = hv;
        }
        __syncthreads();

        // --- Publish: arrive on the rg counter (RED, no return). ---
        if (tid == 0) {
            __threadfence();
            asm volatile("red.release.gpu.global.add.u32 [%0], %1;"
                         :: "l"(cnt), "r"(1u) : "memory");
        }
    }
}

// ---------------------------------------------------------------------------
// inputs: d_in[0]=inputs (B,T,I) f32, d_in[1]=h_prev (B,H) f32,
//         d_in[2]=W_xh (I,H) f32, d_in[3]=W_hh (H,H) f32, d_in[4]=b_h (H) f32
// out: (B,T,H) f32
// ---------------------------------------------------------------------------
extern "C" void kernel_launch(void* const* d_in, const int* in_sizes, int n_in,
                              void* d_out, int out_size) {
    const float* x      = (const float*)d_in[0];
    const float* h_prev = (const float*)d_in[1];
    const float* W_xh   = (const float*)d_in[2];
    const float* W_hh   = (const float*)d_in[3];
    const float* b_h    = (const float*)d_in[4];
    float* out = (float*)d_out;

    (void)in_sizes; (void)n_in; (void)out_size;

    // 128 KB (W) + 80 KB (h^T) + 16.6 KB (pbuf) = 229632 B -> 1 CTA/SM.
    const int smem_bytes = (WS_FLOATS + HS_FLOATS + PB_FLOATS) * 4;
    cudaFuncSetAttribute(rnn_recur, cudaFuncAttributeMaxDynamicSharedMemorySize,
                         smem_bytes);

    xproj_gemm<<<dim3(HH / 128, (BB * TT) / 128), 256>>>(x, W_xh, b_h, h_prev, out);
    rnn_recur<<<128, 256, smem_bytes>>>(W_hh, out);
}

// round 17
// speedup vs baseline: 1.5591x; 1.1241x over previous
#include <cuda_runtime.h>

#define BB 64
#define TT 512
#define II 512
#define HH 1024

// Recurrence tiling: 128 CTAs = 4 row-groups (16 rows) x 32 col-groups (32 cols).
#define RG_ROWS 16
#define CG_COLS 32
#define PB_STRIDE 520                // pbuf plane stride: 16 rows x 32 + 8 pad

#define WS_FLOATS (1024 * CG_COLS)   // 32768 (128 KB)
#define PB_FLOATS (8 * PB_STRIDE)    // 4160  (16.6 KB)

// TRANSPOSED h double buffer: g_ht[buf][col*64 + row]  (col = hidden idx 0..1023,
// row = batch idx 0..63). Consumers read 4 rows of one col as a single float4.
__device__ float g_ht[2][HH * BB];
// Per-row-group monotone barrier counters (256 B apart).
__device__ unsigned g_cnt[4 * 64];

// ---------------------------------------------------------------------------
// Packed f32x2 helpers (Blackwell FFMA2 — only reachable via PTX fma.rn.f32x2).
// ---------------------------------------------------------------------------
__device__ __forceinline__ unsigned long long pack2(float v) {
    unsigned long long r;
    asm("mov.b64 %0, {%1, %1};" : "=l"(r) : "f"(v));
    return r;
}
__device__ __forceinline__ void fma2(unsigned long long& d,
                                     unsigned long long a,
                                     unsigned long long b) {
    asm("fma.rn.f32x2 %0, %1, %2, %0;" : "+l"(d) : "l"(a), "l"(b));
}
__device__ __forceinline__ void add2(unsigned long long& d,
                                     unsigned long long a) {
    asm("add.rn.f32x2 %0, %0, %1;" : "+l"(d) : "l"(a));
}
__device__ __forceinline__ void unpack2(unsigned long long v, float& lo, float& hi) {
    asm("mov.b64 {%0, %1}, %2;" : "=f"(lo), "=f"(hi) : "l"(v));
}
__device__ __forceinline__ unsigned long long dl(double d) {
    return __double_as_longlong(d);
}

// ---------------------------------------------------------------------------
// Phase 1: x_proj = inputs(32768x512) @ W_xh(512x1024) + b  -> written to out.
// 128x128 tile, 8x8 microtile, BK=16, packed FFMA2 inner product.
// CTA (0,0) additionally resets the rg barrier counters and stages h_prev
// TRANSPOSED into ring[0] (stream order guarantees visibility to rnn_recur).
// ---------------------------------------------------------------------------
__global__ __launch_bounds__(256, 2) void xproj_gemm(
    const float* __restrict__ A, const float* __restrict__ W,
    const float* __restrict__ bias, const float* __restrict__ h_prev,
    float* __restrict__ C) {
    __shared__ __align__(16) float As[16][128];   // As[k][m]
    __shared__ __align__(16) float Bs[16][128];   // Bs[k][n]

    const int tid = threadIdx.x;

    // Merged init (one CTA): counters = 0, ring[0] = h_prev transposed.
    if (blockIdx.x == 0 && blockIdx.y == 0) {
        if (tid < 4) g_cnt[tid * 64] = 0u;
        for (int i = 0; i < 256; i++) {
            int idx = tid + i * 256;            // 0..65535
            int row = idx >> 10;                // batch 0..63
            int col = idx & 1023;               // hidden 0..1023
            g_ht[0][col * 64 + row] = h_prev[idx];
        }
    }

    const int m0 = blockIdx.y * 128;
    const int n0 = blockIdx.x * 128;
    const int tx = tid & 15;        // n microtile
    const int ty = tid >> 4;        // m microtile

    const int aRow = tid >> 2;
    const int aK   = (tid & 3) * 4;
    const int bRow = tid >> 5;
    const int bC   = (tid & 31) * 4;

    unsigned long long acc2[8][4];
#pragma unroll
    for (int i = 0; i < 8; i++)
#pragma unroll
        for (int j = 0; j < 4; j++) acc2[i][j] = 0ull;

    for (int k0 = 0; k0 < II; k0 += 16) {
#pragma unroll
        for (int it = 0; it < 2; it++) {
            int row = aRow + it * 64;
            float4 v = *(const float4*)&A[(size_t)(m0 + row) * II + k0 + aK];
            As[aK + 0][row] = v.x;
            As[aK + 1][row] = v.y;
            As[aK + 2][row] = v.z;
            As[aK + 3][row] = v.w;
        }
#pragma unroll
        for (int it = 0; it < 2; it++) {
            int rr = bRow + it * 8;
            *(float4*)&Bs[rr][bC] =
                *(const float4*)&W[(size_t)(k0 + rr) * HH + n0 + bC];
        }
        __syncthreads();
#pragma unroll
        for (int kk = 0; kk < 16; kk++) {
            float a[8];
            *(float4*)&a[0] = *(const float4*)&As[kk][ty * 8];
            *(float4*)&a[4] = *(const float4*)&As[kk][ty * 8 + 4];
            double2 bx = *(const double2*)&Bs[kk][tx * 8];
            double2 by = *(const double2*)&Bs[kk][tx * 8 + 4];
            unsigned long long b01 = dl(bx.x), b23 = dl(bx.y);
            unsigned long long b45 = dl(by.x), b67 = dl(by.y);
#pragma unroll
            for (int i = 0; i < 8; i++) {
                unsigned long long ap = pack2(a[i]);
                fma2(acc2[i][0], ap, b01);
                fma2(acc2[i][1], ap, b23);
                fma2(acc2[i][2], ap, b45);
                fma2(acc2[i][3], ap, b67);
            }
        }
        __syncthreads();
    }

#pragma unroll
    for (int i = 0; i < 8; i++) {
        int row = m0 + ty * 8 + i;
        float c[8];
#pragma unroll
        for (int j = 0; j < 4; j++) unpack2(acc2[i][j], c[2 * j], c[2 * j + 1]);
#pragma unroll
        for (int j = 0; j < 8; j++) c[j] += bias[n0 + tx * 8 + j];
        *(float4*)&C[(size_t)row * HH + n0 + tx * 8]     = *(float4*)&c[0];
        *(float4*)&C[(size_t)row * HH + n0 + tx * 8 + 4] = *(float4*)&c[4];
    }
}

// ---------------------------------------------------------------------------
// Phase 2: persistent recurrence — NO h staging. Producers write h to a
// TRANSPOSED global ring; consumers __ldcg float4s (4 rows at one hidden col)
// straight into a software pipeline feeding FFMA2s on smem-resident W.
//
// CTA (rg, cgp): rows rg*16..+16, cols cgp*32..+32. SMEM: W [1024][32]
// k-major (128 KB, resident) + pbuf 8 planes (16.6 KB) = 145 KB, 1 CTA/SM.
//
// Threads (256): tid = ks(4b)|rbl(2b)|cg(2b). Thread: rows rbl*4..+4, cols
// cg*8..+8, k-range ks*64..+64. Per kk: 1 __ldcg float4 (4 rows at col k;
// 4 cg lanes share the address -> one sector) pipelined 8 deep + 2 W-LDS.128
// (warp broadcast: W read from smem once per step; ks-parity offset keeps
// 1 wavefront/inst) -> 16 FFMA2. Partials: 16 ks-planes fold 16->8 then
// 8-plane reduce; each thread finishes 2 outputs (tanh, store out + ring^T).
// ---------------------------------------------------------------------------
__global__ __launch_bounds__(256, 1) void rnn_recur(
    const float* __restrict__ Whh, float* __restrict__ out) {
    extern __shared__ __align__(16) float smem_dyn[];
    float* ws   = smem_dyn;              // [1024][32] k-major
    float* pbuf = ws + WS_FLOATS;        // [8][520]

    const int tid = threadIdx.x;
    const int cg  = tid & 3;
    const int rbl = (tid >> 2) & 3;
    const int ks  = tid >> 4;
    const int r0  = rbl * 4;
    const int swz = (ks & 1) * 4;        // ks-parity bank offset (cols)
    const int colA = cg * 8 + swz;       // 4 cols covered by first W float4
    const int colB = cg * 8 + (swz ^ 4); // 4 cols covered by second

    const int rg      = blockIdx.x >> 5;
    const int rowbase = rg * RG_ROWS;
    const int colbase = (blockIdx.x & 31) * CG_COLS;
    unsigned* cnt     = &g_cnt[rg * 64];

    // --- Prologue: load W tile (1024 x 32) into smem k-major, once. ---
    {
        const float4* wsrc0 = (const float4*)(Whh + colbase);
        float4* wdst = (float4*)ws;
#pragma unroll
        for (int i = 0; i < 32; i++) {
            int idx4 = tid + i * 256;           // 8192 float4 total
            int k  = idx4 >> 3;                 // 8 float4 per W row
            int c4 = idx4 & 7;
            wdst[idx4] = wsrc0[(size_t)k * (HH / 4) + c4];
        }
    }
    __syncthreads();

    const float* wA = ws + (size_t)(ks * 64) * CG_COLS + colA;
    const float* wB = ws + (size_t)(ks * 64) * CG_COLS + colB;

    // Epilogue mapping: thread finishes 2 outputs (row er, cols ec2, ec2+1).
    const int er  = tid >> 4;               // local row 0..15
    const int ec2 = (tid & 15) * 2;         // local col (even)

    for (int t = 1; t <= TT; t++) {
        // Prefetch x_proj operand (t-indexed only — hidden behind the spin).
        const size_t oidx =
            ((size_t)(rowbase + er) * TT + (t - 1)) * HH + colbase + ec2;
        float2 xp = *(const float2*)&out[oidx];

        // --- Wait: all 32 rg producers have published step t-1. ---
        if (t > 1) {
            if (tid == 0) {
                const unsigned want = 32u * (unsigned)(t - 1);
                unsigned v;
                do {
                    asm volatile("ld.acquire.gpu.global.b32 %0, [%1];"
                                 : "=r"(v) : "l"(cnt) : "memory");
                } while (v < want);
            }
            __syncthreads();
        }

        // h^T source for this thread: col = ks*64 + kk, rows r0..r0+3.
        // float4 stride per kk = 64 floats = 16 float4.
        const float4* hsrc = (const float4*)(
            g_ht[(t - 1) & 1] + ((size_t)ks * 64) * 64 + rowbase + r0);

        // --- Software pipeline: 8-deep h prefetch straight from L2. ---
        float4 hpre[8];
#pragma unroll
        for (int j = 0; j < 8; j++) hpre[j] = __ldcg(hsrc + j * 16);

        unsigned long long acc[4][4];
#pragma unroll
        for (int i = 0; i < 4; i++)
#pragma unroll
            for (int p = 0; p < 4; p++) acc[i][p] = 0ull;

#pragma unroll 8
        for (int kk = 0; kk < 64; kk++) {
            float4 hv = hpre[kk & 7];
            if (kk < 56) hpre[kk & 7] = __ldcg(hsrc + (kk + 8) * 16);
            ulonglong2 a = *(const ulonglong2*)(wA + (size_t)kk * CG_COLS);
            ulonglong2 b = *(const ulonglong2*)(wB + (size_t)kk * CG_COLS);
            unsigned long long hp;
            hp = pack2(hv.x);
            fma2(acc[0][0], hp, a.x); fma2(acc[0][1], hp, a.y);
            fma2(acc[0][2], hp, b.x); fma2(acc[0][3], hp, b.y);
            hp = pack2(hv.y);
            fma2(acc[1][0], hp, a.x); fma2(acc[1][1], hp, a.y);
            fma2(acc[1][2], hp, b.x); fma2(acc[1][3], hp, b.y);
            hp = pack2(hv.z);
            fma2(acc[2][0], hp, a.x); fma2(acc[2][1], hp, a.y);
            fma2(acc[2][2], hp, b.x); fma2(acc[2][3], hp, b.y);
            hp = pack2(hv.w);
            fma2(acc[3][0], hp, a.x); fma2(acc[3][1], hp, a.y);
            fma2(acc[3][2], hp, b.x); fma2(acc[3][3], hp, b.y);
        }

        // --- Fold 16 ks-planes into 8: ks<8 write, then ks>=8 add. ---
        float* plane = pbuf + (size_t)(ks & 7) * PB_STRIDE;
        if (ks < 8) {
#pragma unroll
            for (int i = 0; i < 4; i++) {
                *(ulonglong2*)(plane + (r0 + i) * 32 + colA) =
                    make_ulonglong2(acc[i][0], acc[i][1]);
                *(ulonglong2*)(plane + (r0 + i) * 32 + colB) =
                    make_ulonglong2(acc[i][2], acc[i][3]);
            }
        }
        __syncthreads();
        if (ks >= 8) {
#pragma unroll
            for (int i = 0; i < 4; i++) {
                ulonglong2* pA = (ulonglong2*)(plane + (r0 + i) * 32 + colA);
                ulonglong2* pB = (ulonglong2*)(plane + (r0 + i) * 32 + colB);
                ulonglong2 vA = *pA, vB = *pB;
                add2(vA.x, acc[i][0]); add2(vA.y, acc[i][1]);
                add2(vB.x, acc[i][2]); add2(vB.y, acc[i][3]);
                *pA = vA; *pB = vB;
            }
        }
        __syncthreads();

        // --- 8-plane reduce + tanh + store: out (row-major) + ring^T. ---
        {
            const float* pb = pbuf + (size_t)er * 32 + ec2;
            float sx = xp.x, sy = xp.y;
#pragma unroll
            for (int p = 0; p < 8; p++) {
                float2 s = *(const float2*)(pb + (size_t)p * PB_STRIDE);
                sx += s.x;
                sy += s.y;
            }
            float hx = tanhf(sx);
            float hy = tanhf(sy);
            *(float2*)&out[oidx] = make_float2(hx, hy);
            float* ring = g_ht[t & 1];
            ring[(size_t)(colbase + ec2) * 64 + rowbase + er]     = hx;
            ring[(size_t)(colbase + ec2 + 1) * 64 + rowbase + er] = hy;
        }
        __syncthreads();

        // --- Publish: arrive on the rg counter (RED, no return). ---
        if (tid == 0) {
            __threadfence();
            asm volatile("red.release.gpu.global.add.u32 [%0], %1;"
                         :: "l"(cnt), "r"(1u) : "memory");
        }
    }
}

// ---------------------------------------------------------------------------
// inputs: d_in[0]=inputs (B,T,I) f32, d_in[1]=h_prev (B,H) f32,
//         d_in[2]=W_xh (I,H) f32, d_in[3]=W_hh (H,H) f32, d_in[4]=b_h (H) f32
// out: (B,T,H) f32
// ---------------------------------------------------------------------------
extern "C" void kernel_launch(void* const* d_in, const int* in_sizes, int n_in,
                              void* d_out, int out_size) {
    const float* x      = (const float*)d_in[0];
    const float* h_prev = (const float*)d_in[1];
    const float* W_xh   = (const float*)d_in[2];
    const float* W_hh   = (const float*)d_in[3];
    const float* b_h    = (const float*)d_in[4];
    float* out = (float*)d_out;

    (void)in_sizes; (void)n_in; (void)out_size;

    // 128 KB (W) + 16.6 KB (pbuf) = 147712 B -> 1 CTA/SM.
    const int smem_bytes = (WS_FLOATS + PB_FLOATS) * 4;
    cudaFuncSetAttribute(rnn_recur, cudaFuncAttributeMaxDynamicSharedMemorySize,
                         smem_bytes);

    xproj_gemm<<<dim3(HH / 128, (BB * TT) / 128), 256>>>(x, W_xh, b_h, h_prev, out);
    rnn_recur<<<128, 256, smem_bytes>>>(W_hh, out);
}